// round 2
// baseline (speedup 1.0000x reference)
#include <cuda_runtime.h>
#include <cstdint>

#define N_NODES 20000
#define N_EDGES 640000
#define DIM 128

// ---------------- scratch (no allocations allowed) ----------------
__device__ int   g_is64;
__device__ int   g_deg[N_NODES];
__device__ int   g_off[N_NODES];
__device__ int   g_cur[N_NODES];
__device__ int   g_bucket[N_EDGES];
__device__ float g_H[N_NODES * DIM];
__device__ float g_M[N_NODES * DIM];

// index loader: edge_index may be int32 or int64 depending on jax x64 config
__device__ __forceinline__ int load_idx(const void* ei, int e, int is64) {
    if (is64) return (int)((const long long*)ei)[e];
    return ((const int*)ei)[e];
}

// ---------------- k_pre: zero deg + detect index dtype ----------------
__global__ void k_pre(const void* ei) {
    int gid = blockIdx.x * blockDim.x + threadIdx.x;
    for (int i = gid; i < N_NODES; i += gridDim.x * blockDim.x) g_deg[i] = 0;

    if (blockIdx.x == 0) {
        __shared__ int s_any;
        if (threadIdx.x == 0) s_any = 0;
        __syncthreads();
        // sample odd 32-bit words of the first 4096 (possible) int64 entries.
        // int64 layout (values < 2^31): all high words are 0.
        // int32 layout: words are random src ids in [0,20000) -> ~0 chance all zero.
        const int* w = (const int*)ei;
        int any = 0;
        for (int i = threadIdx.x; i < 4096; i += blockDim.x)
            any |= w[2 * i + 1];
        if (any) atomicOr(&s_any, 1);
        __syncthreads();
        if (threadIdx.x == 0) g_is64 = (s_any == 0) ? 1 : 0;
    }
}

// ---------------- k_hist: out-degree histogram over src ----------------
__global__ void k_hist(const void* ei) {
    int e = blockIdx.x * blockDim.x + threadIdx.x;
    if (e >= N_EDGES) return;
    int is64 = g_is64;
    int s = load_idx(ei, e, is64);
    atomicAdd(&g_deg[s], 1);
}

// ---------------- k_scan: exclusive prefix sum of deg -> off, cur ----------------
__global__ void k_scan() {
    __shared__ int ssum[1024];
    const int CH = 20;  // 1024*20 >= 20000
    int t = threadIdx.x;
    int base = t * CH;
    int s = 0;
#pragma unroll
    for (int i = 0; i < CH; i++) {
        int idx = base + i;
        if (idx < N_NODES) s += g_deg[idx];
    }
    ssum[t] = s;
    __syncthreads();
    for (int ofs = 1; ofs < 1024; ofs <<= 1) {
        int v = (t >= ofs) ? ssum[t - ofs] : 0;
        __syncthreads();
        ssum[t] += v;
        __syncthreads();
    }
    int run = (t == 0) ? 0 : ssum[t - 1];
#pragma unroll
    for (int i = 0; i < CH; i++) {
        int idx = base + i;
        if (idx < N_NODES) {
            g_off[idx] = run;
            g_cur[idx] = run;
            run += g_deg[idx];
        }
    }
}

// ---------------- k_place: alpha output + counting-sort bucket fill ----------------
__global__ void k_place(const void* ei, float* __restrict__ alpha_out) {
    int e = blockIdx.x * blockDim.x + threadIdx.x;
    if (e >= N_EDGES) return;
    int is64 = g_is64;
    int s = load_idx(ei, e, is64);
    int d = load_idx(ei, N_EDGES + e, is64);
    int dg = g_deg[s];
    alpha_out[e] = 1.0f / ((float)dg + 1e-12f);
    int p = atomicAdd(&g_cur[s], 1);
    g_bucket[p] = d;
}

// ---------------- k_mlp: Y = (relu?)(X @ W^T + b), X:[nrows,128], W:[128,128] ----------------
// BM=64, BN=128, BK=32, 256 threads, thread tile 4x8
template <bool RELU>
__global__ void __launch_bounds__(256) k_mlp(const float* __restrict__ X,
                                             const float* __restrict__ W,
                                             const float* __restrict__ bias,
                                             float* __restrict__ Y, int nrows) {
    __shared__ __align__(16) float As[32 * 68];   // [k][row], pad 68
    __shared__ __align__(16) float Bs[32 * 132];  // [k][col], pad 132

    int tid = threadIdx.x;
    int rb = blockIdx.x * 64;
    int tr = tid & 15;   // row group: rows tr*4 .. tr*4+3
    int tc = tid >> 4;   // col group: cols tc*8 .. tc*8+7

    float acc[4][8];
#pragma unroll
    for (int i = 0; i < 4; i++)
#pragma unroll
        for (int j = 0; j < 8; j++) acc[i][j] = 0.f;

    for (int kt = 0; kt < 4; kt++) {
        int k0 = kt * 32;
        // load A tile (64 rows x 32 k), transposed into [k][row]
#pragma unroll
        for (int q = 0; q < 2; q++) {
            int slot = tid * 2 + q;       // 0..511
            int row = slot >> 3;          // 0..63
            int kc = slot & 7;            // 0..7 (float4 group)
            float4 v = make_float4(0.f, 0.f, 0.f, 0.f);
            int gr = rb + row;
            if (gr < nrows)
                v = *reinterpret_cast<const float4*>(X + (size_t)gr * DIM + k0 + kc * 4);
            As[(kc * 4 + 0) * 68 + row] = v.x;
            As[(kc * 4 + 1) * 68 + row] = v.y;
            As[(kc * 4 + 2) * 68 + row] = v.z;
            As[(kc * 4 + 3) * 68 + row] = v.w;
        }
        // load B tile (128 cols x 32 k), transposed into [k][col]
#pragma unroll
        for (int q = 0; q < 4; q++) {
            int slot = tid + 256 * q;     // 0..1023
            int col = slot >> 3;          // 0..127
            int kc = slot & 7;
            float4 v = *reinterpret_cast<const float4*>(W + (size_t)col * DIM + k0 + kc * 4);
            Bs[(kc * 4 + 0) * 132 + col] = v.x;
            Bs[(kc * 4 + 1) * 132 + col] = v.y;
            Bs[(kc * 4 + 2) * 132 + col] = v.z;
            Bs[(kc * 4 + 3) * 132 + col] = v.w;
        }
        __syncthreads();
#pragma unroll
        for (int k = 0; k < 32; k++) {
            float4 a = *reinterpret_cast<float4*>(&As[k * 68 + tr * 4]);
            float4 b0 = *reinterpret_cast<float4*>(&Bs[k * 132 + tc * 8]);
            float4 b1 = *reinterpret_cast<float4*>(&Bs[k * 132 + tc * 8 + 4]);
            float av[4] = {a.x, a.y, a.z, a.w};
            float bv[8] = {b0.x, b0.y, b0.z, b0.w, b1.x, b1.y, b1.z, b1.w};
#pragma unroll
            for (int i = 0; i < 4; i++)
#pragma unroll
                for (int j = 0; j < 8; j++) acc[i][j] += av[i] * bv[j];
        }
        __syncthreads();
    }

    int c0 = tc * 8;
    float4 bb0 = *reinterpret_cast<const float4*>(bias + c0);
    float4 bb1 = *reinterpret_cast<const float4*>(bias + c0 + 4);
    float bv[8] = {bb0.x, bb0.y, bb0.z, bb0.w, bb1.x, bb1.y, bb1.z, bb1.w};
#pragma unroll
    for (int i = 0; i < 4; i++) {
        int gr = rb + tr * 4 + i;
        if (gr < nrows) {
            float o[8];
#pragma unroll
            for (int j = 0; j < 8; j++) {
                float v = acc[i][j] + bv[j];
                if (RELU) v = fmaxf(v, 0.f);
                o[j] = v;
            }
            float4* dst = reinterpret_cast<float4*>(Y + (size_t)gr * DIM + c0);
            dst[0] = make_float4(o[0], o[1], o[2], o[3]);
            dst[1] = make_float4(o[4], o[5], o[6], o[7]);
        }
    }
}

// ---------------- k_agg: gather-sum M[dst], residual, LayerNorm ----------------
__global__ void __launch_bounds__(128) k_agg(const float* __restrict__ z,
                                             const float* __restrict__ gamma,
                                             const float* __restrict__ beta,
                                             float* __restrict__ out) {
    int i = blockIdx.x;
    int t = threadIdx.x;
    __shared__ int nb[128];
    __shared__ float ss[4], sq[4];

    int off = g_off[i];
    int d = g_deg[i];
    float acc = 0.f;

    for (int base = 0; base < d; base += 128) {
        int c = d - base;
        if (c > 128) c = 128;
        if (t < c) nb[t] = g_bucket[off + base + t];
        __syncthreads();
        int j = 0;
        for (; j + 4 <= c; j += 4) {
            int n0 = nb[j], n1 = nb[j + 1], n2 = nb[j + 2], n3 = nb[j + 3];
            float a0 = g_M[n0 * DIM + t];
            float a1 = g_M[n1 * DIM + t];
            float a2 = g_M[n2 * DIM + t];
            float a3 = g_M[n3 * DIM + t];
            acc += (a0 + a1) + (a2 + a3);
        }
        for (; j < c; j++) acc += g_M[nb[j] * DIM + t];
        __syncthreads();
    }

    float r = 1.0f / ((float)d + 1e-12f);
    float x = z[(size_t)i * DIM + t] + acc * r;

    float s = x, q = x * x;
#pragma unroll
    for (int o = 16; o > 0; o >>= 1) {
        s += __shfl_xor_sync(0xFFFFFFFFu, s, o);
        q += __shfl_xor_sync(0xFFFFFFFFu, q, o);
    }
    if ((t & 31) == 0) { ss[t >> 5] = s; sq[t >> 5] = q; }
    __syncthreads();
    s = ss[0] + ss[1] + ss[2] + ss[3];
    q = sq[0] + sq[1] + sq[2] + sq[3];
    float mu = s * (1.0f / 128.0f);
    float var = q * (1.0f / 128.0f) - mu * mu;
    float inv = rsqrtf(var + 1e-5f);
    out[(size_t)i * DIM + t] = (x - mu) * inv * gamma[t] + beta[t];
}

// ---------------- launch ----------------
extern "C" void kernel_launch(void* const* d_in, const int* in_sizes, int n_in,
                              void* d_out, int out_size) {
    const float* z = (const float*)d_in[0];
    const void* ei = d_in[1];
    const float* W1 = (const float*)d_in[2];
    const float* b1 = (const float*)d_in[3];
    const float* W2 = (const float*)d_in[4];
    const float* b2 = (const float*)d_in[5];
    const float* gamma = (const float*)d_in[6];
    const float* beta = (const float*)d_in[7];
    float* out = (float*)d_out;
    float* alpha = out + (size_t)N_NODES * DIM;

    float* Hp = nullptr;
    float* Mp = nullptr;
    cudaGetSymbolAddress((void**)&Hp, g_H);
    cudaGetSymbolAddress((void**)&Mp, g_M);

    const int EB = (N_EDGES + 255) / 256;

    k_pre<<<80, 256>>>(ei);
    k_hist<<<EB, 256>>>(ei);
    k_scan<<<1, 1024>>>();
    k_place<<<EB, 256>>>(ei, alpha);
    k_mlp<true><<<(N_NODES + 63) / 64, 256>>>(z, W1, b1, Hp, N_NODES);
    k_mlp<false><<<(N_NODES + 63) / 64, 256>>>(Hp, W2, b2, Mp, N_NODES);
    k_agg<<<N_NODES, 128>>>(z, gamma, beta, out);
}

// round 3
// speedup vs baseline: 1.0102x; 1.0102x over previous
#include <cuda_runtime.h>
#include <cstdint>

#define N_NODES 20000
#define N_EDGES 640000
#define DIM 128

// ---------------- scratch (no allocations allowed) ----------------
__device__ int   g_is64;
__device__ int   g_deg[N_NODES];
__device__ int   g_off[N_NODES];
__device__ int   g_cur[N_NODES];
__device__ int   g_bucket[N_EDGES];
__device__ float g_H[N_NODES * DIM];
__device__ float g_M[N_NODES * DIM];

// index loader: edge_index may be int32 or int64 depending on jax x64 config
__device__ __forceinline__ int load_idx(const void* ei, int e, int is64) {
    if (is64) return (int)((const long long*)ei)[e];
    return ((const int*)ei)[e];
}

// ---------------- k_pre: zero deg + detect index dtype ----------------
__global__ void k_pre(const void* ei) {
    int gid = blockIdx.x * blockDim.x + threadIdx.x;
    for (int i = gid; i < N_NODES; i += gridDim.x * blockDim.x) g_deg[i] = 0;

    if (blockIdx.x == 0) {
        __shared__ int s_any;
        if (threadIdx.x == 0) s_any = 0;
        __syncthreads();
        // sample odd 32-bit words of the first 4096 (possible) int64 entries.
        // int64 layout (values < 2^31): all high words are 0.
        // int32 layout: words are random src ids in [0,20000) -> ~0 chance all zero.
        const int* w = (const int*)ei;
        int any = 0;
        for (int i = threadIdx.x; i < 4096; i += blockDim.x)
            any |= w[2 * i + 1];
        if (any) atomicOr(&s_any, 1);
        __syncthreads();
        if (threadIdx.x == 0) g_is64 = (s_any == 0) ? 1 : 0;
    }
}

// ---------------- k_hist: out-degree histogram over src ----------------
__global__ void k_hist(const void* ei) {
    int e = blockIdx.x * blockDim.x + threadIdx.x;
    if (e >= N_EDGES) return;
    int is64 = g_is64;
    int s = load_idx(ei, e, is64);
    atomicAdd(&g_deg[s], 1);
}

// ---------------- k_scan: exclusive prefix sum of deg -> off, cur ----------------
__global__ void k_scan() {
    __shared__ int ssum[1024];
    const int CH = 20;  // 1024*20 >= 20000
    int t = threadIdx.x;
    int base = t * CH;
    int s = 0;
#pragma unroll
    for (int i = 0; i < CH; i++) {
        int idx = base + i;
        if (idx < N_NODES) s += g_deg[idx];
    }
    ssum[t] = s;
    __syncthreads();
    for (int ofs = 1; ofs < 1024; ofs <<= 1) {
        int v = (t >= ofs) ? ssum[t - ofs] : 0;
        __syncthreads();
        ssum[t] += v;
        __syncthreads();
    }
    int run = (t == 0) ? 0 : ssum[t - 1];
#pragma unroll
    for (int i = 0; i < CH; i++) {
        int idx = base + i;
        if (idx < N_NODES) {
            g_off[idx] = run;
            g_cur[idx] = run;
            run += g_deg[idx];
        }
    }
}

// ---------------- k_place: alpha output + counting-sort bucket fill ----------------
__global__ void k_place(const void* ei, float* __restrict__ alpha_out) {
    int e = blockIdx.x * blockDim.x + threadIdx.x;
    if (e >= N_EDGES) return;
    int is64 = g_is64;
    int s = load_idx(ei, e, is64);
    int d = load_idx(ei, N_EDGES + e, is64);
    int dg = g_deg[s];
    alpha_out[e] = 1.0f / ((float)dg + 1e-12f);
    int p = atomicAdd(&g_cur[s], 1);
    g_bucket[p] = d;
}

// ---------------- k_mlp: Y = (relu?)(X @ W^T + b), X:[nrows,128], W:[128,128] ----------------
// BM=64, BN=128, BK=32, 256 threads, thread tile 4x8
template <bool RELU>
__global__ void __launch_bounds__(256) k_mlp(const float* __restrict__ X,
                                             const float* __restrict__ W,
                                             const float* __restrict__ bias,
                                             float* __restrict__ Y, int nrows) {
    __shared__ __align__(16) float As[32 * 68];   // [k][row], pad 68
    __shared__ __align__(16) float Bs[32 * 132];  // [k][col], pad 132

    int tid = threadIdx.x;
    int rb = blockIdx.x * 64;
    int tr = tid & 15;   // row group: rows tr*4 .. tr*4+3
    int tc = tid >> 4;   // col group: cols tc*8 .. tc*8+7

    float acc[4][8];
#pragma unroll
    for (int i = 0; i < 4; i++)
#pragma unroll
        for (int j = 0; j < 8; j++) acc[i][j] = 0.f;

    for (int kt = 0; kt < 4; kt++) {
        int k0 = kt * 32;
        // load A tile (64 rows x 32 k), transposed into [k][row]
#pragma unroll
        for (int q = 0; q < 2; q++) {
            int slot = tid * 2 + q;       // 0..511
            int row = slot >> 3;          // 0..63
            int kc = slot & 7;            // 0..7 (float4 group)
            float4 v = make_float4(0.f, 0.f, 0.f, 0.f);
            int gr = rb + row;
            if (gr < nrows)
                v = *reinterpret_cast<const float4*>(X + (size_t)gr * DIM + k0 + kc * 4);
            As[(kc * 4 + 0) * 68 + row] = v.x;
            As[(kc * 4 + 1) * 68 + row] = v.y;
            As[(kc * 4 + 2) * 68 + row] = v.z;
            As[(kc * 4 + 3) * 68 + row] = v.w;
        }
        // load B tile (128 cols x 32 k), transposed into [k][col]
#pragma unroll
        for (int q = 0; q < 4; q++) {
            int slot = tid + 256 * q;     // 0..1023
            int col = slot >> 3;          // 0..127
            int kc = slot & 7;
            float4 v = *reinterpret_cast<const float4*>(W + (size_t)col * DIM + k0 + kc * 4);
            Bs[(kc * 4 + 0) * 132 + col] = v.x;
            Bs[(kc * 4 + 1) * 132 + col] = v.y;
            Bs[(kc * 4 + 2) * 132 + col] = v.z;
            Bs[(kc * 4 + 3) * 132 + col] = v.w;
        }
        __syncthreads();
#pragma unroll
        for (int k = 0; k < 32; k++) {
            float4 a = *reinterpret_cast<float4*>(&As[k * 68 + tr * 4]);
            float4 b0 = *reinterpret_cast<float4*>(&Bs[k * 132 + tc * 8]);
            float4 b1 = *reinterpret_cast<float4*>(&Bs[k * 132 + tc * 8 + 4]);
            float av[4] = {a.x, a.y, a.z, a.w};
            float bv[8] = {b0.x, b0.y, b0.z, b0.w, b1.x, b1.y, b1.z, b1.w};
#pragma unroll
            for (int i = 0; i < 4; i++)
#pragma unroll
                for (int j = 0; j < 8; j++) acc[i][j] += av[i] * bv[j];
        }
        __syncthreads();
    }

    int c0 = tc * 8;
    float4 bb0 = *reinterpret_cast<const float4*>(bias + c0);
    float4 bb1 = *reinterpret_cast<const float4*>(bias + c0 + 4);
    float bv[8] = {bb0.x, bb0.y, bb0.z, bb0.w, bb1.x, bb1.y, bb1.z, bb1.w};
#pragma unroll
    for (int i = 0; i < 4; i++) {
        int gr = rb + tr * 4 + i;
        if (gr < nrows) {
            float o[8];
#pragma unroll
            for (int j = 0; j < 8; j++) {
                float v = acc[i][j] + bv[j];
                if (RELU) v = fmaxf(v, 0.f);
                o[j] = v;
            }
            float4* dst = reinterpret_cast<float4*>(Y + (size_t)gr * DIM + c0);
            dst[0] = make_float4(o[0], o[1], o[2], o[3]);
            dst[1] = make_float4(o[4], o[5], o[6], o[7]);
        }
    }
}

// ---------------- k_agg: gather-sum M[dst], residual, LayerNorm ----------------
__global__ void __launch_bounds__(128) k_agg(const float* __restrict__ z,
                                             const float* __restrict__ gamma,
                                             const float* __restrict__ beta,
                                             float* __restrict__ out) {
    int i = blockIdx.x;
    int t = threadIdx.x;
    __shared__ int nb[128];
    __shared__ float ss[4], sq[4];

    int off = g_off[i];
    int d = g_deg[i];
    float acc = 0.f;

    for (int base = 0; base < d; base += 128) {
        int c = d - base;
        if (c > 128) c = 128;
        if (t < c) nb[t] = g_bucket[off + base + t];
        __syncthreads();
        int j = 0;
        for (; j + 4 <= c; j += 4) {
            int n0 = nb[j], n1 = nb[j + 1], n2 = nb[j + 2], n3 = nb[j + 3];
            float a0 = g_M[n0 * DIM + t];
            float a1 = g_M[n1 * DIM + t];
            float a2 = g_M[n2 * DIM + t];
            float a3 = g_M[n3 * DIM + t];
            acc += (a0 + a1) + (a2 + a3);
        }
        for (; j < c; j++) acc += g_M[nb[j] * DIM + t];
        __syncthreads();
    }

    float r = 1.0f / ((float)d + 1e-12f);
    float x = z[(size_t)i * DIM + t] + acc * r;

    float s = x, q = x * x;
#pragma unroll
    for (int o = 16; o > 0; o >>= 1) {
        s += __shfl_xor_sync(0xFFFFFFFFu, s, o);
        q += __shfl_xor_sync(0xFFFFFFFFu, q, o);
    }
    if ((t & 31) == 0) { ss[t >> 5] = s; sq[t >> 5] = q; }
    __syncthreads();
    s = ss[0] + ss[1] + ss[2] + ss[3];
    q = sq[0] + sq[1] + sq[2] + sq[3];
    float mu = s * (1.0f / 128.0f);
    float var = q * (1.0f / 128.0f) - mu * mu;
    float inv = rsqrtf(var + 1e-5f);
    out[(size_t)i * DIM + t] = (x - mu) * inv * gamma[t] + beta[t];
}

// ---------------- launch ----------------
extern "C" void kernel_launch(void* const* d_in, const int* in_sizes, int n_in,
                              void* d_out, int out_size) {
    const float* z = (const float*)d_in[0];
    const void* ei = d_in[1];
    const float* W1 = (const float*)d_in[2];
    const float* b1 = (const float*)d_in[3];
    const float* W2 = (const float*)d_in[4];
    const float* b2 = (const float*)d_in[5];
    const float* gamma = (const float*)d_in[6];
    const float* beta = (const float*)d_in[7];
    float* out = (float*)d_out;
    float* alpha = out + (size_t)N_NODES * DIM;

    float* Hp = nullptr;
    float* Mp = nullptr;
    cudaGetSymbolAddress((void**)&Hp, g_H);
    cudaGetSymbolAddress((void**)&Mp, g_M);

    const int EB = (N_EDGES + 255) / 256;

    k_pre<<<80, 256>>>(ei);
    k_hist<<<EB, 256>>>(ei);
    k_scan<<<1, 1024>>>();
    k_place<<<EB, 256>>>(ei, alpha);
    k_mlp<true><<<(N_NODES + 63) / 64, 256>>>(z, W1, b1, Hp, N_NODES);
    k_mlp<false><<<(N_NODES + 63) / 64, 256>>>(Hp, W2, b2, Mp, N_NODES);
    k_agg<<<N_NODES, 128>>>(z, gamma, beta, out);
}